// round 6
// baseline (speedup 1.0000x reference)
#include <cuda_runtime.h>

#define B_TOT    8192
#define T_LEN    512
#define F_IN     24
#define H_DIM    12
#define CHUNK    8
#define EPB      4            // batch elements per block (one warp, 8 lanes each)
#define NTHREADS 32
#define NCHUNK   (T_LEN / CHUNK)
#define XS_STRIDE 24          // floats per (tt,elem) x row (natural, conflict-free)
#define HPAD     24           // floats per elem in h buffer (12 used + pad)
#define XS_BUF_FLOATS (CHUNK * EPB * XS_STRIDE)   // 768
#define SMEM_BYTES (2 * XS_BUF_FLOATS * 4)        // 6144

typedef unsigned long long u64;

__device__ __forceinline__ unsigned smem_u32(const void* p) {
    return (unsigned)__cvta_generic_to_shared(p);
}
__device__ __forceinline__ void cp_async16(unsigned dst, const void* src) {
    asm volatile("cp.async.cg.shared.global [%0], [%1], 16;\n" :: "r"(dst), "l"(src));
}
__device__ __forceinline__ void cp_commit() {
    asm volatile("cp.async.commit_group;\n" ::: "memory");
}
template <int N> __device__ __forceinline__ void cp_wait() {
    asm volatile("cp.async.wait_group %0;\n" :: "n"(N) : "memory");
}

// ---- packed f32x2 helpers ----
__device__ __forceinline__ u64 pack2(float lo, float hi) {
    u64 d; asm("mov.b64 %0, {%1, %2};" : "=l"(d) : "f"(lo), "f"(hi)); return d;
}
__device__ __forceinline__ void unpack2(u64 d, float& lo, float& hi) {
    asm("mov.b64 {%0, %1}, %2;" : "=f"(lo), "=f"(hi) : "l"(d));
}
__device__ __forceinline__ u64 fma2(u64 a, u64 b, u64 c) {
    u64 d; asm("fma.rn.f32x2 %0, %1, %2, %3;" : "=l"(d) : "l"(a), "l"(b), "l"(c)); return d;
}
__device__ __forceinline__ u64 add2(u64 a, u64 b) {
    u64 d; asm("add.rn.f32x2 %0, %1, %2;" : "=l"(d) : "l"(a), "l"(b)); return d;
}
__device__ __forceinline__ float hadd2(u64 a) {
    float lo, hi; unpack2(a, lo, hi); return lo + hi;
}

// tanh(x) = 1 - 2*rcp(exp(2x)+1); 5 instrs, correct saturation at +/-inf.
__device__ __forceinline__ float tanh_fast(float x) {
    float e;
    asm("ex2.approx.f32 %0, %1;" : "=f"(e) : "f"(x * 2.885390082f));
    float r;
    asm("rcp.approx.f32 %0, %1;" : "=f"(r) : "f"(e + 1.0f));
    return fmaf(-2.0f, r, 1.0f);
}

__global__ void __launch_bounds__(NTHREADS) rnn_fused_kernel(
    const float* __restrict__ x,
    const float* __restrict__ W_ih, const float* __restrict__ b_ih,
    const float* __restrict__ W_hh, const float* __restrict__ b_hh,
    const float* __restrict__ W1,   const float* __restrict__ b1,
    const float* __restrict__ W2,   const float* __restrict__ b2,
    const float* __restrict__ W3,   const float* __restrict__ b3,
    float* __restrict__ out)
{
    extern __shared__ float xs[];                   // [2][CHUNK][EPB][24]
    __shared__ float hsm[2 * EPB * HPAD];           // double-buffered h
    __shared__ float sW1[144], sW2[144], sb1[12], sb2[12], sW3[12], sb3[1];

    const int tid  = threadIdx.x;
    const int e    = tid >> 3;          // element (0..3)
    const int p    = (tid >> 2) & 1;    // contraction half
    const int s    = tid & 3;           // row triple: rows 3s..3s+2
    const int j0   = s * 3;

    for (int i = tid; i < 144; i += NTHREADS) { sW1[i] = W1[i]; sW2[i] = W2[i]; }
    if (tid < 12) { sb1[tid] = b1[tid]; sb2[tid] = b2[tid]; sW3[tid] = W3[tid]; }
    if (tid == 0) sb3[0] = b3[0];
    for (int i = tid; i < 2 * EPB * HPAD; i += NTHREADS) hsm[i] = 0.0f;

    // ---- per-lane weights ----
    // iproj: feature 16B-chunks {p, p+2, p+4} -> pairs (2*(p+2k)+m)
    u64 wih2[3][6];
    #pragma unroll
    for (int r = 0; r < 3; r++) {
        const int j = j0 + r;
        #pragma unroll
        for (int k = 0; k < 3; k++) {
            const int P0 = 2 * (p + 2 * k);       // pair index base for chunk
            wih2[r][2 * k + 0] = pack2(W_ih[j * F_IN + 2 * P0],     W_ih[j * F_IN + 2 * P0 + 1]);
            wih2[r][2 * k + 1] = pack2(W_ih[j * F_IN + 2 * P0 + 2], W_ih[j * F_IN + 2 * P0 + 3]);
        }
    }
    // rec: h pairs {2p, 2p+1, 4+p}  (matches LDS.128@16p and LDS.64@32+8p)
    u64 whh2[3][3], biasp[3];
    #pragma unroll
    for (int r = 0; r < 3; r++) {
        const int j = j0 + r;
        const int q0 = 2 * p, q1 = 2 * p + 1, q2 = 4 + p;
        whh2[r][0] = pack2(W_hh[j * H_DIM + 2 * q0], W_hh[j * H_DIM + 2 * q0 + 1]);
        whh2[r][1] = pack2(W_hh[j * H_DIM + 2 * q1], W_hh[j * H_DIM + 2 * q1 + 1]);
        whh2[r][2] = pack2(W_hh[j * H_DIM + 2 * q2], W_hh[j * H_DIM + 2 * q2 + 1]);
        biasp[r] = (p == 0) ? pack2(b_ih[j] + b_hh[j], 0.0f) : 0ull;
    }

    // ---- cp.async staging: lane l stages row (tt=l>>2, es=l&3): 96B contiguous ----
    const int es = tid & 3;
    const long b_stage = (long)blockIdx.x * EPB + es;
    const float* src0 = x + (b_stage * T_LEN + (tid >> 2)) * F_IN;
    const unsigned xsb = smem_u32(xs);
    const unsigned dst0 = xsb + (unsigned)(tid * (XS_STRIDE * 4));

    auto load_chunk = [&](int bufidx, int c) {
        const float* sp = src0 + (long)c * (CHUNK * F_IN);
        const unsigned d = dst0 + (unsigned)bufidx * (XS_BUF_FLOATS * 4);
        #pragma unroll
        for (int q = 0; q < 6; q++)
            cp_async16(d + (unsigned)(q * 16), sp + q * 4);
        cp_commit();
    };

    const unsigned hbase_e = smem_u32(hsm) + (unsigned)(e * HPAD * 4);
    float* hW0 = hsm + e * HPAD + j0;              // write slots (slot 0)
    const unsigned hL128 = hbase_e + (unsigned)(p * 16);
    const unsigned hL64  = hbase_e + 32u + (unsigned)(p * 8);
    const unsigned SLOT  = (unsigned)(EPB * HPAD * 4);   // byte offset slot0->slot1

    load_chunk(0, 0);
    __syncwarp();   // zeros in hsm visible

    for (int c = 0; c < NCHUNK; c++) {
        if (c + 1 < NCHUNK) { load_chunk((c + 1) & 1, c + 1); cp_wait<1>(); }
        else                { cp_wait<0>(); }
        __syncwarp();  // all lanes' x data for chunk c visible

        const float* buf = xs + (c & 1) * XS_BUF_FLOATS;

        #pragma unroll
        for (int tt = 0; tt < CHUNK; tt++) {
            const unsigned rd = (tt & 1) ? SLOT : 0u;      // read slot parity
            const unsigned wr = (tt & 1) ? 0u : SLOT;      // write other slot

            // x: 3 LDS.128 -> 6 packed pairs (this lane's feature half)
            const float* xrow = buf + (tt * EPB + e) * XS_STRIDE;
            ulonglong2 xv[3];
            #pragma unroll
            for (int k = 0; k < 3; k++)
                xv[k] = *(const ulonglong2*)(xrow + (p + 2 * k) * 4);

            u64 a0 = biasp[0], a1 = biasp[1], a2 = biasp[2];
            #pragma unroll
            for (int k = 0; k < 3; k++) {
                a0 = fma2(wih2[0][2 * k + 0], xv[k].x, a0);
                a1 = fma2(wih2[1][2 * k + 0], xv[k].x, a1);
                a2 = fma2(wih2[2][2 * k + 0], xv[k].x, a2);
                a0 = fma2(wih2[0][2 * k + 1], xv[k].y, a0);
                a1 = fma2(wih2[1][2 * k + 1], xv[k].y, a1);
                a2 = fma2(wih2[2][2 * k + 1], xv[k].y, a2);
            }

            // h: LDS.128 (pairs 2p,2p+1) + LDS.64 (pair 4+p)
            u64 hq0, hq1, hq2;
            asm volatile("ld.shared.v2.b64 {%0, %1}, [%2];"
                         : "=l"(hq0), "=l"(hq1) : "r"(hL128 + rd));
            asm volatile("ld.shared.b64 %0, [%1];"
                         : "=l"(hq2) : "r"(hL64 + rd));

            u64 r0 = fma2(whh2[0][0], hq0, (u64)0);
            u64 r1 = fma2(whh2[1][0], hq0, (u64)0);
            u64 r2 = fma2(whh2[2][0], hq0, (u64)0);
            r0 = fma2(whh2[0][1], hq1, r0);
            r1 = fma2(whh2[1][1], hq1, r1);
            r2 = fma2(whh2[2][1], hq1, r2);
            r0 = fma2(whh2[0][2], hq2, r0);
            r1 = fma2(whh2[1][2], hq2, r1);
            r2 = fma2(whh2[2][2], hq2, r2);

            float p0 = hadd2(add2(a0, r0));
            float p1 = hadd2(add2(a1, r1));
            float p2 = hadd2(add2(a2, r2));
            // combine the two contraction halves (partner lane = lane ^ 4)
            p0 += __shfl_xor_sync(0xffffffffu, p0, 4);
            p1 += __shfl_xor_sync(0xffffffffu, p1, 4);
            p2 += __shfl_xor_sync(0xffffffffu, p2, 4);

            float h0 = tanh_fast(p0);
            float h1 = tanh_fast(p1);
            float h2 = tanh_fast(p2);

            if (p == 0) {   // one half publishes (conflict-free STS.32 x3)
                float* w = (float*)((char*)hW0 + wr);
                w[0] = h0; w[1] = h1; w[2] = h2;
            }
            __syncwarp();   // new h visible before next step reads it
        }
    }

    // MLP head: lane (s==0, p==0) of each element; final h is in slot 0
    if ((tid & 7) == 0) {
        const float* hrow = hsm + e * HPAD;   // slot 0
        float h_all[H_DIM];
        #pragma unroll
        for (int k = 0; k < H_DIM; k++) h_all[k] = hrow[k];
        float o1[H_DIM], o2[H_DIM];
        #pragma unroll
        for (int j = 0; j < H_DIM; j++) {
            float t = sb1[j];
            #pragma unroll
            for (int k = 0; k < H_DIM; k++) t = fmaf(sW1[j * H_DIM + k], h_all[k], t);
            o1[j] = fmaxf(t, 0.0f);
        }
        #pragma unroll
        for (int j = 0; j < H_DIM; j++) {
            float t = sb2[j];
            #pragma unroll
            for (int k = 0; k < H_DIM; k++) t = fmaf(sW2[j * H_DIM + k], o1[k], t);
            o2[j] = fmaxf(t, 0.0f);
        }
        float t = sb3[0];
        #pragma unroll
        for (int k = 0; k < H_DIM; k++) t = fmaf(sW3[k], o2[k], t);
        out[blockIdx.x * EPB + e] = t;
    }
}

extern "C" void kernel_launch(void* const* d_in, const int* in_sizes, int n_in,
                              void* d_out, int out_size) {
    (void)in_sizes; (void)n_in; (void)out_size;
    const float* x    = (const float*)d_in[0];
    const float* W_ih = (const float*)d_in[1];
    const float* b_ih = (const float*)d_in[2];
    const float* W_hh = (const float*)d_in[3];
    const float* b_hh = (const float*)d_in[4];
    const float* W1   = (const float*)d_in[5];
    const float* b1   = (const float*)d_in[6];
    const float* W2   = (const float*)d_in[7];
    const float* b2   = (const float*)d_in[8];
    const float* W3   = (const float*)d_in[9];
    const float* b3   = (const float*)d_in[10];
    float* out = (float*)d_out;

    cudaFuncSetAttribute(rnn_fused_kernel,
                         cudaFuncAttributeMaxDynamicSharedMemorySize, SMEM_BYTES);

    dim3 grid(B_TOT / EPB);   // 2048 single-warp blocks
    dim3 block(NTHREADS);
    rnn_fused_kernel<<<grid, block, SMEM_BYTES>>>(
        x, W_ih, b_ih, W_hh, b_hh, W1, b1, W2, b2, W3, b3, out);
}